// round 5
// baseline (speedup 1.0000x reference)
#include <cuda_runtime.h>
#include <cuda_bf16.h>
#include <math.h>

#define BB 64
#define SS 512
#define HH 1024
#define G4 4096  // 4*H

// ---------------- static device scratch (no runtime allocs allowed) ----------
__device__ float g_xproj[(size_t)SS * BB * G4];          // [t][b][4H] fp32, 512 MB
__device__ __nv_bfloat16 g_wihi[(size_t)G4 * HH];        // Wi split hi  [4096][1024]
__device__ __nv_bfloat16 g_wilo[(size_t)G4 * HH];        // Wi split lo
__device__ __nv_bfloat16 g_whhi[(size_t)G4 * HH];        // Wh split hi
__device__ __nv_bfloat16 g_whlo[(size_t)G4 * HH];        // Wh split lo
__device__ __nv_bfloat16 g_hhi[2][BB * HH];              // h split hi, double buffered
__device__ __nv_bfloat16 g_hlo[2][BB * HH];              // h split lo
__device__ float g_c[BB * HH];                           // cell state fp32
__device__ float g_hf32[BB * HH];                        // final h fp32 (written at t=S-1)
__device__ float g_bias[G4];                             // b_i + b_h fused

// ---------------------------------------------------------------------------
__device__ __forceinline__ void bsplit(float x, __nv_bfloat16& hi, __nv_bfloat16& lo) {
    hi = __float2bfloat16(x);
    lo = __float2bfloat16(x - __bfloat162float(hi));
}

__device__ __forceinline__ void mma16816(float* d, const unsigned* a, const unsigned* b) {
    asm volatile(
        "mma.sync.aligned.m16n8k16.row.col.f32.bf16.bf16.f32 "
        "{%0,%1,%2,%3}, {%4,%5,%6,%7}, {%8,%9}, {%0,%1,%2,%3};\n"
        : "+f"(d[0]), "+f"(d[1]), "+f"(d[2]), "+f"(d[3])
        : "r"(a[0]), "r"(a[1]), "r"(a[2]), "r"(a[3]), "r"(b[0]), "r"(b[1]));
}

// ---------------------------------------------------------------------------
// split 4 gate weight matrices (each 1024x1024 f32) into concatenated hi/lo bf16 [4096][1024]
__global__ void split4_kernel(__nv_bfloat16* __restrict__ dhi, __nv_bfloat16* __restrict__ dlo,
                              const float* __restrict__ p0, const float* __restrict__ p1,
                              const float* __restrict__ p2, const float* __restrict__ p3) {
    size_t i = (size_t)blockIdx.x * blockDim.x + threadIdx.x;
    if (i >= (size_t)G4 * HH) return;
    int g = (int)(i >> 20);  // i / (1024*1024)
    size_t r = i & ((1u << 20) - 1);
    const float* p = (g == 0) ? p0 : (g == 1) ? p1 : (g == 2) ? p2 : p3;
    __nv_bfloat16 hi, lo;
    bsplit(p[r], hi, lo);
    dhi[i] = hi;
    dlo[i] = lo;
}

__global__ void bias_init_kernel(const float* __restrict__ bii, const float* __restrict__ bif,
                                 const float* __restrict__ big, const float* __restrict__ bio,
                                 const float* __restrict__ bhi, const float* __restrict__ bhf,
                                 const float* __restrict__ bhg, const float* __restrict__ bho) {
    int i = blockIdx.x * blockDim.x + threadIdx.x;
    if (i >= G4) return;
    int g = i >> 10, j = i & 1023;
    const float* bi = (g == 0) ? bii : (g == 1) ? bif : (g == 2) ? big : bio;
    const float* bh = (g == 0) ? bhi : (g == 1) ? bhf : (g == 2) ? bhg : bho;
    g_bias[i] = bi[j] + bh[j];
}

__global__ void init_state_kernel(const float* __restrict__ h0, const float* __restrict__ c0) {
    int i = blockIdx.x * blockDim.x + threadIdx.x;
    if (i >= BB * HH) return;
    __nv_bfloat16 hi, lo;
    bsplit(h0[i], hi, lo);
    g_hhi[0][i] = hi;
    g_hlo[0][i] = lo;
    g_c[i] = c0[i];
}

// ---------------------------------------------------------------------------
// GEMM1 (tensor): xproj[(s*64+b)*4096 + n] = sum_k X[b][s][k] * Wi[n][k] + bias[n]
// Logical M = 32768 (m -> b = m&63, s = m>>6), N = 4096, K = 1024, 3-way bf16 split.
// Block: 128m x 128n, BK = 32, 256 threads, 8 warps (4 m x 2 n), warp tile 32x64.
#define PADK 40  // smem row stride in bf16 elements (conflict-free frag loads)
__global__ void gemm1_kernel(const float* __restrict__ X) {
    __shared__ __nv_bfloat16 Ahi[128][PADK], Alo[128][PADK];
    __shared__ __nv_bfloat16 Bhi[128][PADK], Blo[128][PADK];

    const int tid = threadIdx.x;
    const int wid = tid >> 5, lane = tid & 31;
    const int grp = lane >> 2, tig = lane & 3;
    const int warpm = (wid & 3) * 32;      // 0,32,64,96
    const int warpn = (wid >> 2) * 64;     // 0,64
    const int m0 = blockIdx.y * 128;
    const int n0 = blockIdx.x * 128;

    float acc[2][8][4];
#pragma unroll
    for (int mt = 0; mt < 2; mt++)
#pragma unroll
        for (int nt = 0; nt < 8; nt++)
#pragma unroll
            for (int q = 0; q < 4; q++) acc[mt][nt][q] = 0.f;

    // loader indices
    const int lr = tid >> 1;           // 0..127
    const int lkq = (tid & 1) * 16;    // 0 or 16

    for (int k0 = 0; k0 < HH; k0 += 32) {
        // --- load A (X) 128x32 f32 -> split into Ahi/Alo ---
        {
            int m = m0 + lr;
            int b = m & 63, s = m >> 6;
            const float* src = &X[(size_t)(b * SS + s) * HH + k0 + lkq];
#pragma unroll
            for (int u = 0; u < 4; u++) {
                float4 v = *reinterpret_cast<const float4*>(src + 4 * u);
                __nv_bfloat16 h0x, l0x, h1x, l1x, h2x, l2x, h3x, l3x;
                bsplit(v.x, h0x, l0x); bsplit(v.y, h1x, l1x);
                bsplit(v.z, h2x, l2x); bsplit(v.w, h3x, l3x);
                int c = lkq + 4 * u;
                Ahi[lr][c + 0] = h0x; Ahi[lr][c + 1] = h1x; Ahi[lr][c + 2] = h2x; Ahi[lr][c + 3] = h3x;
                Alo[lr][c + 0] = l0x; Alo[lr][c + 1] = l1x; Alo[lr][c + 2] = l2x; Alo[lr][c + 3] = l3x;
            }
        }
        // --- load B (Wi splits) 128x32 bf16 each ---
        {
            int n = n0 + lr;
            const __nv_bfloat16* shi = &g_wihi[(size_t)n * HH + k0 + lkq];
            const __nv_bfloat16* slo = &g_wilo[(size_t)n * HH + k0 + lkq];
#pragma unroll
            for (int u = 0; u < 2; u++) {
                uint4 vh = *reinterpret_cast<const uint4*>(shi + 8 * u);
                uint4 vl = *reinterpret_cast<const uint4*>(slo + 8 * u);
                *reinterpret_cast<uint4*>(&Bhi[lr][lkq + 8 * u]) = vh;
                *reinterpret_cast<uint4*>(&Blo[lr][lkq + 8 * u]) = vl;
            }
        }
        __syncthreads();

        // --- 3 split passes: (Ahi,Bhi), (Alo,Bhi), (Ahi,Blo) ---
#pragma unroll
        for (int pass = 0; pass < 3; pass++) {
            const __nv_bfloat16(*As)[PADK] = (pass == 1) ? Alo : Ahi;
            const __nv_bfloat16(*Bs)[PADK] = (pass == 2) ? Blo : Bhi;
#pragma unroll
            for (int k16 = 0; k16 < 32; k16 += 16) {
                unsigned a[2][4];
#pragma unroll
                for (int mt = 0; mt < 2; mt++) {
                    int rb = warpm + mt * 16;
                    a[mt][0] = *reinterpret_cast<const unsigned*>(&As[rb + grp][k16 + 2 * tig]);
                    a[mt][1] = *reinterpret_cast<const unsigned*>(&As[rb + grp + 8][k16 + 2 * tig]);
                    a[mt][2] = *reinterpret_cast<const unsigned*>(&As[rb + grp][k16 + 2 * tig + 8]);
                    a[mt][3] = *reinterpret_cast<const unsigned*>(&As[rb + grp + 8][k16 + 2 * tig + 8]);
                }
#pragma unroll
                for (int nt = 0; nt < 8; nt++) {
                    unsigned b[2];
                    int nr = warpn + nt * 8 + grp;
                    b[0] = *reinterpret_cast<const unsigned*>(&Bs[nr][k16 + 2 * tig]);
                    b[1] = *reinterpret_cast<const unsigned*>(&Bs[nr][k16 + 2 * tig + 8]);
                    mma16816(acc[0][nt], a[0], b);
                    mma16816(acc[1][nt], a[1], b);
                }
            }
        }
        __syncthreads();
    }

    // --- epilogue: write xproj + bias ---
#pragma unroll
    for (int mt = 0; mt < 2; mt++) {
#pragma unroll
        for (int nt = 0; nt < 8; nt++) {
            int n = n0 + warpn + nt * 8 + 2 * tig;
            float bia0 = g_bias[n], bia1 = g_bias[n + 1];
            int mA = m0 + warpm + mt * 16 + grp;
            int mB = mA + 8;
            size_t rA = (size_t)mA * G4;
            size_t rB = (size_t)mB * G4;
            g_xproj[rA + n] = acc[mt][nt][0] + bia0;
            g_xproj[rA + n + 1] = acc[mt][nt][1] + bia1;
            g_xproj[rB + n] = acc[mt][nt][2] + bia0;
            g_xproj[rB + n + 1] = acc[mt][nt][3] + bia1;
        }
    }
}

// ---------------------------------------------------------------------------
// Step kernel (tensor): one timestep. Block owns hidden units [j0, j0+8) for all
// 4 gates -> 32 gemm cols, all 64 batch rows. Grid = 128 blocks, 256 threads.
// gemm col c -> n = (c>>3)*1024 + j0 + (c&7).
__global__ void step_kernel(float* __restrict__ out, int t) {
    __shared__ __nv_bfloat16 Ahi[64][PADK], Alo[64][PADK];
    __shared__ __nv_bfloat16 Bhi[32][PADK], Blo[32][PADK];
    __shared__ float gsm[64][32];

    const int tid = threadIdx.x;
    const int wid = tid >> 5, lane = tid & 31;
    const int grp = lane >> 2, tig = lane & 3;
    const int warpm = (wid & 1) * 32;     // 0,32
    const int warpn = (wid >> 1) * 8;     // 0,8,16,24
    const int j0 = blockIdx.x * 8;
    const int buf = t & 1;

    const __nv_bfloat16* __restrict__ hhi = g_hhi[buf];
    const __nv_bfloat16* __restrict__ hlo = g_hlo[buf];

    float acc[2][4];
#pragma unroll
    for (int mt = 0; mt < 2; mt++)
#pragma unroll
        for (int q = 0; q < 4; q++) acc[mt][q] = 0.f;

    // loader indices: A: 64 rows x 32 halves, 256 threads -> 8 halves each
    const int ar = tid >> 2;          // 0..63
    const int akq = (tid & 3) * 8;    // 0,8,16,24
    // B: 32 rows x 32 halves x 2 arrays: tid<128 -> hi, tid>=128 -> lo
    const int bt = tid & 127;
    const int br = bt >> 2;           // 0..31
    const int bkq = (bt & 3) * 8;
    const int bn = (br >> 3) * 1024 + j0 + (br & 7);  // global Wh row for col br
    const bool bhiSide = (tid < 128);

    for (int k0 = 0; k0 < HH; k0 += 32) {
        {
            uint4 vh = *reinterpret_cast<const uint4*>(&hhi[ar * HH + k0 + akq]);
            uint4 vl = *reinterpret_cast<const uint4*>(&hlo[ar * HH + k0 + akq]);
            *reinterpret_cast<uint4*>(&Ahi[ar][akq]) = vh;
            *reinterpret_cast<uint4*>(&Alo[ar][akq]) = vl;
        }
        {
            const __nv_bfloat16* src = bhiSide ? &g_whhi[(size_t)bn * HH + k0 + bkq]
                                               : &g_whlo[(size_t)bn * HH + k0 + bkq];
            uint4 v = *reinterpret_cast<const uint4*>(src);
            if (bhiSide) *reinterpret_cast<uint4*>(&Bhi[br][bkq]) = v;
            else         *reinterpret_cast<uint4*>(&Blo[br][bkq]) = v;
        }
        __syncthreads();

#pragma unroll
        for (int pass = 0; pass < 3; pass++) {
            const __nv_bfloat16(*As)[PADK] = (pass == 1) ? Alo : Ahi;
            const __nv_bfloat16(*Bs)[PADK] = (pass == 2) ? Blo : Bhi;
#pragma unroll
            for (int k16 = 0; k16 < 32; k16 += 16) {
                unsigned b[2];
                b[0] = *reinterpret_cast<const unsigned*>(&Bs[warpn + grp][k16 + 2 * tig]);
                b[1] = *reinterpret_cast<const unsigned*>(&Bs[warpn + grp][k16 + 2 * tig + 8]);
#pragma unroll
                for (int mt = 0; mt < 2; mt++) {
                    int rb = warpm + mt * 16;
                    unsigned a[4];
                    a[0] = *reinterpret_cast<const unsigned*>(&As[rb + grp][k16 + 2 * tig]);
                    a[1] = *reinterpret_cast<const unsigned*>(&As[rb + grp + 8][k16 + 2 * tig]);
                    a[2] = *reinterpret_cast<const unsigned*>(&As[rb + grp][k16 + 2 * tig + 8]);
                    a[3] = *reinterpret_cast<const unsigned*>(&As[rb + grp + 8][k16 + 2 * tig + 8]);
                    mma16816(acc[mt], a, b);
                }
            }
        }
        __syncthreads();
    }

    // stage gate gemm results to smem
#pragma unroll
    for (int mt = 0; mt < 2; mt++) {
        int rb = warpm + mt * 16;
        gsm[rb + grp][warpn + 2 * tig] = acc[mt][0];
        gsm[rb + grp][warpn + 2 * tig + 1] = acc[mt][1];
        gsm[rb + grp + 8][warpn + 2 * tig] = acc[mt][2];
        gsm[rb + grp + 8][warpn + 2 * tig + 1] = acc[mt][3];
    }
    __syncthreads();

    // pointwise LSTM update: 512 units, 2 per thread
    const int nb = (t + 1) & 1;
#pragma unroll
    for (int uu = 0; uu < 2; uu++) {
        int u = tid + uu * 256;
        int m = u >> 3;
        int jj = u & 7;
        size_t xb = (size_t)(t * BB + m) * G4;
        float gi = gsm[m][jj] + g_xproj[xb + j0 + jj];
        float gf = gsm[m][8 + jj] + g_xproj[xb + 1024 + j0 + jj];
        float gg = gsm[m][16 + jj] + g_xproj[xb + 2048 + j0 + jj];
        float go = gsm[m][24 + jj] + g_xproj[xb + 3072 + j0 + jj];
        float si = 1.f / (1.f + __expf(-gi));
        float sf = 1.f / (1.f + __expf(-gf));
        float tg = tanhf(gg);
        float so = 1.f / (1.f + __expf(-go));
        int idx = m * HH + j0 + jj;
        float cn = sf * g_c[idx] + si * tg;
        g_c[idx] = cn;
        float hn = so * tanhf(cn);
        out[((size_t)m * SS + t) * HH + j0 + jj] = hn;
        __nv_bfloat16 hi, lo;
        bsplit(hn, hi, lo);
        g_hhi[nb][idx] = hi;
        g_hlo[nb][idx] = lo;
        if (t == SS - 1) g_hf32[idx] = hn;
    }
}

// final h/c copy into the output tail
__global__ void finalize_kernel(float* __restrict__ out) {
    int i = blockIdx.x * blockDim.x + threadIdx.x;
    if (i >= BB * HH) return;
    size_t base = (size_t)BB * SS * HH;
    out[base + i] = g_hf32[i];
    out[base + BB * HH + i] = g_c[i];
}

// ---------------------------------------------------------------------------
extern "C" void kernel_launch(void* const* d_in, const int* in_sizes, int n_in,
                              void* d_out, int out_size) {
    const float* inputs = (const float*)d_in[0];
    const float* h0 = (const float*)d_in[1];
    const float* c0 = (const float*)d_in[2];
    const float* w_ii = (const float*)d_in[3];
    const float* w_if = (const float*)d_in[4];
    const float* w_ig = (const float*)d_in[5];
    const float* w_io = (const float*)d_in[6];
    const float* b_ii = (const float*)d_in[7];
    const float* b_if = (const float*)d_in[8];
    const float* b_ig = (const float*)d_in[9];
    const float* b_io = (const float*)d_in[10];
    const float* w_hi = (const float*)d_in[11];
    const float* w_hf = (const float*)d_in[12];
    const float* w_hg = (const float*)d_in[13];
    const float* w_ho = (const float*)d_in[14];
    const float* b_hi = (const float*)d_in[15];
    const float* b_hf = (const float*)d_in[16];
    const float* b_hg = (const float*)d_in[17];
    const float* b_ho = (const float*)d_in[18];
    float* out = (float*)d_out;

    // weight pre-splits (hi/lo bf16)
    __nv_bfloat16 *wihi, *wilo, *whhi, *whlo;
    cudaGetSymbolAddress((void**)&wihi, g_wihi);
    cudaGetSymbolAddress((void**)&wilo, g_wilo);
    cudaGetSymbolAddress((void**)&whhi, g_whhi);
    cudaGetSymbolAddress((void**)&whlo, g_whlo);

    int nW = G4 * HH;
    split4_kernel<<<(nW + 255) / 256, 256>>>(wihi, wilo, w_ii, w_if, w_ig, w_io);
    split4_kernel<<<(nW + 255) / 256, 256>>>(whhi, whlo, w_hi, w_hf, w_hg, w_ho);
    bias_init_kernel<<<16, 256>>>(b_ii, b_if, b_ig, b_io, b_hi, b_hf, b_hg, b_ho);
    init_state_kernel<<<256, 256>>>(h0, c0);

    // x projection for the whole sequence (tensor cores)
    dim3 g1grid(32, 256);
    gemm1_kernel<<<g1grid, 256>>>(inputs);

    // sequential recurrence
    for (int t = 0; t < SS; t++) {
        step_kernel<<<128, 256>>>(out, t);
    }

    if (out_size >= BB * SS * HH + 2 * BB * HH) {
        finalize_kernel<<<256, 256>>>(out);
    }
}

// round 12
// speedup vs baseline: 1.2740x; 1.2740x over previous
#include <cuda_runtime.h>
#include <cuda_bf16.h>
#include <math.h>

#define BB 64
#define SS 512
#define HH 1024
#define G4 4096  // 4*H
#define NBLK 128

// ---------------- static device scratch (no runtime allocs allowed) ----------
__device__ float g_xproj[(size_t)SS * BB * G4];          // [t][b][4H] fp32, 512 MB
__device__ __nv_bfloat16 g_wihi[(size_t)G4 * HH];        // Wi split hi  [4096][1024]
__device__ __nv_bfloat16 g_wilo[(size_t)G4 * HH];        // Wi split lo
__device__ __nv_bfloat16 g_whhi[(size_t)G4 * HH];        // Wh split hi
__device__ __nv_bfloat16 g_whlo[(size_t)G4 * HH];        // Wh split lo
__device__ __nv_bfloat16 g_hhi[2][BB * HH];              // h split hi, double buffered
__device__ __nv_bfloat16 g_hlo[2][BB * HH];              // h split lo
__device__ float g_c[BB * HH];                           // cell state fp32
__device__ float g_hf32[BB * HH];                        // final h fp32 (written at t=S-1)
__device__ float g_bias[G4];                             // b_i + b_h fused
__device__ unsigned g_arrive;                            // grid barrier arrivals (cumulative)
__device__ volatile unsigned g_epoch;                    // completed-step counter

// ---------------------------------------------------------------------------
__device__ __forceinline__ void bsplit(float x, __nv_bfloat16& hi, __nv_bfloat16& lo) {
    hi = __float2bfloat16(x);
    lo = __float2bfloat16(x - __bfloat162float(hi));
}

__device__ __forceinline__ void mma16816(float* d, const unsigned* a, const unsigned* b) {
    asm volatile(
        "mma.sync.aligned.m16n8k16.row.col.f32.bf16.bf16.f32 "
        "{%0,%1,%2,%3}, {%4,%5,%6,%7}, {%8,%9}, {%0,%1,%2,%3};\n"
        : "+f"(d[0]), "+f"(d[1]), "+f"(d[2]), "+f"(d[3])
        : "r"(a[0]), "r"(a[1]), "r"(a[2]), "r"(a[3]), "r"(b[0]), "r"(b[1]));
}

__device__ __forceinline__ unsigned smem_u32(const void* p) {
    return (unsigned)__cvta_generic_to_shared(p);
}
__device__ __forceinline__ void ldsm_x4(unsigned* r, unsigned addr) {
    asm volatile("ldmatrix.sync.aligned.m8n8.x4.shared.b16 {%0,%1,%2,%3}, [%4];\n"
                 : "=r"(r[0]), "=r"(r[1]), "=r"(r[2]), "=r"(r[3]) : "r"(addr));
}
__device__ __forceinline__ void ldsm_x2(unsigned* r, unsigned addr) {
    asm volatile("ldmatrix.sync.aligned.m8n8.x2.shared.b16 {%0,%1}, [%2];\n"
                 : "=r"(r[0]), "=r"(r[1]) : "r"(addr));
}

// ---------------------------------------------------------------------------
__global__ void split4_kernel(__nv_bfloat16* __restrict__ dhi, __nv_bfloat16* __restrict__ dlo,
                              const float* __restrict__ p0, const float* __restrict__ p1,
                              const float* __restrict__ p2, const float* __restrict__ p3) {
    size_t i = (size_t)blockIdx.x * blockDim.x + threadIdx.x;
    if (i >= (size_t)G4 * HH) return;
    int g = (int)(i >> 20);
    size_t r = i & ((1u << 20) - 1);
    const float* p = (g == 0) ? p0 : (g == 1) ? p1 : (g == 2) ? p2 : p3;
    __nv_bfloat16 hi, lo;
    bsplit(p[r], hi, lo);
    dhi[i] = hi;
    dlo[i] = lo;
}

__global__ void bias_init_kernel(const float* __restrict__ bii, const float* __restrict__ bif,
                                 const float* __restrict__ big, const float* __restrict__ bio,
                                 const float* __restrict__ bhi, const float* __restrict__ bhf,
                                 const float* __restrict__ bhg, const float* __restrict__ bho) {
    int i = blockIdx.x * blockDim.x + threadIdx.x;
    if (i >= G4) return;
    int g = i >> 10, j = i & 1023;
    const float* bi = (g == 0) ? bii : (g == 1) ? bif : (g == 2) ? big : bio;
    const float* bh = (g == 0) ? bhi : (g == 1) ? bhf : (g == 2) ? bhg : bho;
    g_bias[i] = bi[j] + bh[j];
}

__global__ void init_state_kernel(const float* __restrict__ h0, const float* __restrict__ c0) {
    int i = blockIdx.x * blockDim.x + threadIdx.x;
    if (i >= BB * HH) return;
    __nv_bfloat16 hi, lo;
    bsplit(h0[i], hi, lo);
    g_hhi[0][i] = hi;
    g_hlo[0][i] = lo;
    g_c[i] = c0[i];
    if (i == 0) { g_arrive = 0; g_epoch = 0; }
}

// ---------------------------------------------------------------------------
// GEMM1 (tensor): xproj[m*4096 + n] = sum_k X[b][s][k]*Wi[n][k] + bias[n], m=(s*64+b)
#define PADK 40
__global__ void gemm1_kernel(const float* __restrict__ X) {
    __shared__ __nv_bfloat16 Ahi[128][PADK], Alo[128][PADK];
    __shared__ __nv_bfloat16 Bhi[128][PADK], Blo[128][PADK];

    const int tid = threadIdx.x;
    const int wid = tid >> 5, lane = tid & 31;
    const int grp = lane >> 2, tig = lane & 3;
    const int warpm = (wid & 3) * 32;
    const int warpn = (wid >> 2) * 64;
    const int m0 = blockIdx.y * 128;
    const int n0 = blockIdx.x * 128;

    float acc[2][8][4];
#pragma unroll
    for (int mt = 0; mt < 2; mt++)
#pragma unroll
        for (int nt = 0; nt < 8; nt++)
#pragma unroll
            for (int q = 0; q < 4; q++) acc[mt][nt][q] = 0.f;

    const int lr = tid >> 1;
    const int lkq = (tid & 1) * 16;

    for (int k0 = 0; k0 < HH; k0 += 32) {
        {
            int m = m0 + lr;
            int b = m & 63, s = m >> 6;
            const float* src = &X[(size_t)(b * SS + s) * HH + k0 + lkq];
#pragma unroll
            for (int u = 0; u < 4; u++) {
                float4 v = *reinterpret_cast<const float4*>(src + 4 * u);
                __nv_bfloat16 h0x, l0x, h1x, l1x, h2x, l2x, h3x, l3x;
                bsplit(v.x, h0x, l0x); bsplit(v.y, h1x, l1x);
                bsplit(v.z, h2x, l2x); bsplit(v.w, h3x, l3x);
                int c = lkq + 4 * u;
                Ahi[lr][c + 0] = h0x; Ahi[lr][c + 1] = h1x; Ahi[lr][c + 2] = h2x; Ahi[lr][c + 3] = h3x;
                Alo[lr][c + 0] = l0x; Alo[lr][c + 1] = l1x; Alo[lr][c + 2] = l2x; Alo[lr][c + 3] = l3x;
            }
        }
        {
            int n = n0 + lr;
            const __nv_bfloat16* shi = &g_wihi[(size_t)n * HH + k0 + lkq];
            const __nv_bfloat16* slo = &g_wilo[(size_t)n * HH + k0 + lkq];
#pragma unroll
            for (int u = 0; u < 2; u++) {
                uint4 vh = *reinterpret_cast<const uint4*>(shi + 8 * u);
                uint4 vl = *reinterpret_cast<const uint4*>(slo + 8 * u);
                *reinterpret_cast<uint4*>(&Bhi[lr][lkq + 8 * u]) = vh;
                *reinterpret_cast<uint4*>(&Blo[lr][lkq + 8 * u]) = vl;
            }
        }
        __syncthreads();

#pragma unroll
        for (int k16 = 0; k16 < 32; k16 += 16) {
            unsigned ahi[2][4], alo[2][4];
#pragma unroll
            for (int mt = 0; mt < 2; mt++) {
                int rb = warpm + mt * 16;
                ahi[mt][0] = *reinterpret_cast<const unsigned*>(&Ahi[rb + grp][k16 + 2 * tig]);
                ahi[mt][1] = *reinterpret_cast<const unsigned*>(&Ahi[rb + grp + 8][k16 + 2 * tig]);
                ahi[mt][2] = *reinterpret_cast<const unsigned*>(&Ahi[rb + grp][k16 + 2 * tig + 8]);
                ahi[mt][3] = *reinterpret_cast<const unsigned*>(&Ahi[rb + grp + 8][k16 + 2 * tig + 8]);
                alo[mt][0] = *reinterpret_cast<const unsigned*>(&Alo[rb + grp][k16 + 2 * tig]);
                alo[mt][1] = *reinterpret_cast<const unsigned*>(&Alo[rb + grp + 8][k16 + 2 * tig]);
                alo[mt][2] = *reinterpret_cast<const unsigned*>(&Alo[rb + grp][k16 + 2 * tig + 8]);
                alo[mt][3] = *reinterpret_cast<const unsigned*>(&Alo[rb + grp + 8][k16 + 2 * tig + 8]);
            }
#pragma unroll
            for (int nt = 0; nt < 8; nt++) {
                int nr = warpn + nt * 8 + grp;
                unsigned bhi[2], blo[2];
                bhi[0] = *reinterpret_cast<const unsigned*>(&Bhi[nr][k16 + 2 * tig]);
                bhi[1] = *reinterpret_cast<const unsigned*>(&Bhi[nr][k16 + 2 * tig + 8]);
                blo[0] = *reinterpret_cast<const unsigned*>(&Blo[nr][k16 + 2 * tig]);
                blo[1] = *reinterpret_cast<const unsigned*>(&Blo[nr][k16 + 2 * tig + 8]);
                mma16816(acc[0][nt], ahi[0], bhi);
                mma16816(acc[1][nt], ahi[1], bhi);
                mma16816(acc[0][nt], alo[0], bhi);
                mma16816(acc[1][nt], alo[1], bhi);
                mma16816(acc[0][nt], ahi[0], blo);
                mma16816(acc[1][nt], ahi[1], blo);
            }
        }
        __syncthreads();
    }

#pragma unroll
    for (int mt = 0; mt < 2; mt++) {
#pragma unroll
        for (int nt = 0; nt < 8; nt++) {
            int n = n0 + warpn + nt * 8 + 2 * tig;
            float bia0 = g_bias[n], bia1 = g_bias[n + 1];
            int mA = m0 + warpm + mt * 16 + grp;
            int mB = mA + 8;
            size_t rA = (size_t)mA * G4;
            size_t rB = (size_t)mB * G4;
            g_xproj[rA + n] = acc[mt][nt][0] + bia0;
            g_xproj[rA + n + 1] = acc[mt][nt][1] + bia1;
            g_xproj[rB + n] = acc[mt][nt][2] + bia0;
            g_xproj[rB + n + 1] = acc[mt][nt][3] + bia1;
        }
    }
}

// ---------------------------------------------------------------------------
// Persistent recurrence kernel: all 512 timesteps in one launch.
// 128 blocks x 256 threads, block owns hidden units [j0,j0+8) x 4 gates = 32 cols.
// Wh slice (hi+lo) resident in dynamic SMEM for the whole kernel.
#define RS_BHI 0
#define RS_BLO 66048
#define RS_AHI 132096
#define RS_ALO 141312
#define RS_GSM 150528
#define RS_TOTAL 158720

__global__ void __launch_bounds__(256, 1) recur_kernel(float* __restrict__ out) {
    extern __shared__ unsigned char sm[];
    __nv_bfloat16(*Bhi)[1032] = reinterpret_cast<__nv_bfloat16(*)[1032]>(sm + RS_BHI);
    __nv_bfloat16(*Blo)[1032] = reinterpret_cast<__nv_bfloat16(*)[1032]>(sm + RS_BLO);
    __nv_bfloat16(*Ahi)[72] = reinterpret_cast<__nv_bfloat16(*)[72]>(sm + RS_AHI);
    __nv_bfloat16(*Alo)[72] = reinterpret_cast<__nv_bfloat16(*)[72]>(sm + RS_ALO);
    float(*gsm)[32] = reinterpret_cast<float(*)[32]>(sm + RS_GSM);

    const int tid = threadIdx.x;
    const int wid = tid >> 5, lane = tid & 31;
    const int grp = lane >> 2, tig = lane & 3;
    const int warpm = (wid & 1) * 32;   // 0,32
    const int warpn = (wid >> 1) * 8;   // 0,8,16,24
    const int j0 = blockIdx.x * 8;

    // ---- load resident Wh slice (hi+lo), once ----
#pragma unroll
    for (int i = 0; i < 16; i++) {
        int idx = tid + i * 256;            // 4096 uint4 per split
        int row = idx >> 7;                 // 0..31
        int c8 = (idx & 127) * 8;           // bf16 col
        int bn = (row >> 3) * 1024 + j0 + (row & 7);
        *reinterpret_cast<uint4*>(&Bhi[row][c8]) =
            *reinterpret_cast<const uint4*>(&g_whhi[(size_t)bn * HH + c8]);
        *reinterpret_cast<uint4*>(&Blo[row][c8]) =
            *reinterpret_cast<const uint4*>(&g_whlo[(size_t)bn * HH + c8]);
    }
    __syncthreads();

    // ldmatrix lane addressing (constant over loop)
    const int arow = (lane & 7) + ((lane >> 3) & 1) * 8;
    const int acol8 = (lane >> 4) * 8;
    const int brow = warpn + (lane & 7);
    const int bcol8 = ((lane >> 3) & 1) * 8;

    const unsigned aHiB0 = smem_u32(&Ahi[warpm + arow][acol8]);
    const unsigned aHiB1 = smem_u32(&Ahi[warpm + 16 + arow][acol8]);
    const unsigned aLoB0 = smem_u32(&Alo[warpm + arow][acol8]);
    const unsigned aLoB1 = smem_u32(&Alo[warpm + 16 + arow][acol8]);
    const unsigned bHiB = smem_u32(&Bhi[brow][bcol8]);
    const unsigned bLoB = smem_u32(&Blo[brow][bcol8]);

    for (int t = 0; t < SS; t++) {
        const int buf = t & 1;
        const __nv_bfloat16* __restrict__ hhi = g_hhi[buf];
        const __nv_bfloat16* __restrict__ hlo = g_hlo[buf];

        float acc[2][4];
#pragma unroll
        for (int mt = 0; mt < 2; mt++)
#pragma unroll
            for (int q = 0; q < 4; q++) acc[mt][q] = 0.f;

        for (int kc = 0; kc < 16; kc++) {
            const int k0 = kc * 64;
            // stage h chunk (L2-only loads: L1 is stale across steps)
#pragma unroll
            for (int u = 0; u < 2; u++) {
                int v = tid + u * 256;
                int row = v >> 3;
                int c8 = (v & 7) * 8;
                uint4 vh = __ldcg(reinterpret_cast<const uint4*>(&hhi[row * HH + k0 + c8]));
                uint4 vl = __ldcg(reinterpret_cast<const uint4*>(&hlo[row * HH + k0 + c8]));
                *reinterpret_cast<uint4*>(&Ahi[row][c8]) = vh;
                *reinterpret_cast<uint4*>(&Alo[row][c8]) = vl;
            }
            __syncthreads();

#pragma unroll
            for (int k16 = 0; k16 < 4; k16++) {
                const unsigned aoff = k16 * 32;            // 16 bf16 = 32 B
                const unsigned boff = (k0 + k16 * 16) * 2; // global k byte offset
                unsigned ah0[4], ah1[4], al0[4], al1[4], bh[2], bl[2];
                ldsm_x4(ah0, aHiB0 + aoff);
                ldsm_x4(ah1, aHiB1 + aoff);
                ldsm_x4(al0, aLoB0 + aoff);
                ldsm_x4(al1, aLoB1 + aoff);
                ldsm_x2(bh, bHiB + boff);
                ldsm_x2(bl, bLoB + boff);
                mma16816(acc[0], ah0, bh);
                mma16816(acc[1], ah1, bh);
                mma16816(acc[0], al0, bh);
                mma16816(acc[1], al1, bh);
                mma16816(acc[0], ah0, bl);
                mma16816(acc[1], ah1, bl);
            }
            __syncthreads();
        }

        // stage gate results
#pragma unroll
        for (int mt = 0; mt < 2; mt++) {
            int rb = warpm + mt * 16;
            gsm[rb + grp][warpn + 2 * tig] = acc[mt][0];
            gsm[rb + grp][warpn + 2 * tig + 1] = acc[mt][1];
            gsm[rb + grp + 8][warpn + 2 * tig] = acc[mt][2];
            gsm[rb + grp + 8][warpn + 2 * tig + 1] = acc[mt][3];
        }
        __syncthreads();

        // pointwise LSTM update: 512 units, 2 per thread
        const int nb = (t + 1) & 1;
#pragma unroll
        for (int uu = 0; uu < 2; uu++) {
            int u = tid + uu * 256;
            int m = u >> 3;
            int jj = u & 7;
            size_t xb = (size_t)(t * BB + m) * G4;
            float gi = gsm[m][jj] + g_xproj[xb + j0 + jj];
            float gf = gsm[m][8 + jj] + g_xproj[xb + 1024 + j0 + jj];
            float gg = gsm[m][16 + jj] + g_xproj[xb + 2048 + j0 + jj];
            float go = gsm[m][24 + jj] + g_xproj[xb + 3072 + j0 + jj];
            float si = 1.f / (1.f + __expf(-gi));
            float sf = 1.f / (1.f + __expf(-gf));
            float tg = tanhf(gg);
            float so = 1.f / (1.f + __expf(-go));
            int idx = m * HH + j0 + jj;
            float cn = sf * g_c[idx] + si * tg;
            g_c[idx] = cn;
            float hn = so * tanhf(cn);
            out[((size_t)m * SS + t) * HH + j0 + jj] = hn;
            __nv_bfloat16 hi, lo;
            bsplit(hn, hi, lo);
            g_hhi[nb][idx] = hi;
            g_hlo[nb][idx] = lo;
            if (t == SS - 1) g_hf32[idx] = hn;
        }

        if (t == SS - 1) break;  // no barrier needed after last step

        // ---- grid barrier: release h writes, wait for all blocks ----
        __threadfence();
        __syncthreads();
        if (tid == 0) {
            unsigned v = atomicAdd(&g_arrive, 1u) + 1u;
            if (v == (unsigned)(t + 1) * NBLK) {
                __threadfence();
                g_epoch = (unsigned)(t + 1);
            } else {
                while (g_epoch <= (unsigned)t) __nanosleep(64);
            }
            __threadfence();
        }
        __syncthreads();
    }
}

// final h/c copy into the output tail
__global__ void finalize_kernel(float* __restrict__ out) {
    int i = blockIdx.x * blockDim.x + threadIdx.x;
    if (i >= BB * HH) return;
    size_t base = (size_t)BB * SS * HH;
    out[base + i] = g_hf32[i];
    out[base + BB * HH + i] = g_c[i];
}

// ---------------------------------------------------------------------------
extern "C" void kernel_launch(void* const* d_in, const int* in_sizes, int n_in,
                              void* d_out, int out_size) {
    const float* inputs = (const float*)d_in[0];
    const float* h0 = (const float*)d_in[1];
    const float* c0 = (const float*)d_in[2];
    const float* w_ii = (const float*)d_in[3];
    const float* w_if = (const float*)d_in[4];
    const float* w_ig = (const float*)d_in[5];
    const float* w_io = (const float*)d_in[6];
    const float* b_ii = (const float*)d_in[7];
    const float* b_if = (const float*)d_in[8];
    const float* b_ig = (const float*)d_in[9];
    const float* b_io = (const float*)d_in[10];
    const float* w_hi = (const float*)d_in[11];
    const float* w_hf = (const float*)d_in[12];
    const float* w_hg = (const float*)d_in[13];
    const float* w_ho = (const float*)d_in[14];
    const float* b_hi = (const float*)d_in[15];
    const float* b_hf = (const float*)d_in[16];
    const float* b_hg = (const float*)d_in[17];
    const float* b_ho = (const float*)d_in[18];
    float* out = (float*)d_out;

    __nv_bfloat16 *wihi, *wilo, *whhi, *whlo;
    cudaGetSymbolAddress((void**)&wihi, g_wihi);
    cudaGetSymbolAddress((void**)&wilo, g_wilo);
    cudaGetSymbolAddress((void**)&whhi, g_whhi);
    cudaGetSymbolAddress((void**)&whlo, g_whlo);

    // not stream-ordered; idempotent and deterministic on every call
    cudaFuncSetAttribute(recur_kernel, cudaFuncAttributeMaxDynamicSharedMemorySize, RS_TOTAL);

    int nW = G4 * HH;
    split4_kernel<<<(nW + 255) / 256, 256>>>(wihi, wilo, w_ii, w_if, w_ig, w_io);
    split4_kernel<<<(nW + 255) / 256, 256>>>(whhi, whlo, w_hi, w_hf, w_hg, w_ho);
    bias_init_kernel<<<16, 256>>>(b_ii, b_if, b_ig, b_io, b_hi, b_hf, b_hg, b_ho);
    init_state_kernel<<<256, 256>>>(h0, c0);

    // x projection for the whole sequence (tensor cores)
    dim3 g1grid(32, 256);
    gemm1_kernel<<<g1grid, 256>>>(inputs);

    // persistent recurrence (all 512 steps)
    recur_kernel<<<NBLK, 256, RS_TOTAL>>>(out);

    if (out_size >= BB * SS * HH + 2 * BB * HH) {
        finalize_kernel<<<256, 256>>>(out);
    }
}

// round 16
// speedup vs baseline: 1.6060x; 1.2605x over previous
#include <cuda_runtime.h>
#include <cuda_bf16.h>
#include <math.h>

#define BB 64
#define SS 512
#define HH 1024
#define G4 4096  // 4*H
#define NBLK 128

// ---------------- static device scratch (no runtime allocs allowed) ----------
__device__ float g_xproj[(size_t)SS * BB * G4];          // [t][b][4H] fp32, 512 MB
__device__ __nv_bfloat16 g_wihi[(size_t)G4 * HH];
__device__ __nv_bfloat16 g_wilo[(size_t)G4 * HH];
__device__ __nv_bfloat16 g_whhi[(size_t)G4 * HH];
__device__ __nv_bfloat16 g_whlo[(size_t)G4 * HH];
__device__ __nv_bfloat16 g_hhi[2][BB * HH];
__device__ __nv_bfloat16 g_hlo[2][BB * HH];
__device__ float g_c[BB * HH];
__device__ float g_hf32[BB * HH];
__device__ float g_bias[G4];
__device__ unsigned g_arrive;
__device__ volatile unsigned g_epoch;

// ---------------------------------------------------------------------------
__device__ __forceinline__ void bsplit(float x, __nv_bfloat16& hi, __nv_bfloat16& lo) {
    hi = __float2bfloat16(x);
    lo = __float2bfloat16(x - __bfloat162float(hi));
}

__device__ __forceinline__ void mma16816(float* d, const unsigned* a, const unsigned* b) {
    asm volatile(
        "mma.sync.aligned.m16n8k16.row.col.f32.bf16.bf16.f32 "
        "{%0,%1,%2,%3}, {%4,%5,%6,%7}, {%8,%9}, {%0,%1,%2,%3};\n"
        : "+f"(d[0]), "+f"(d[1]), "+f"(d[2]), "+f"(d[3])
        : "r"(a[0]), "r"(a[1]), "r"(a[2]), "r"(a[3]), "r"(b[0]), "r"(b[1]));
}

__device__ __forceinline__ unsigned smem_u32(const void* p) {
    return (unsigned)__cvta_generic_to_shared(p);
}
__device__ __forceinline__ void ldsm_x4(unsigned* r, unsigned addr) {
    asm volatile("ldmatrix.sync.aligned.m8n8.x4.shared.b16 {%0,%1,%2,%3}, [%4];\n"
                 : "=r"(r[0]), "=r"(r[1]), "=r"(r[2]), "=r"(r[3]) : "r"(addr));
}
__device__ __forceinline__ void ldsm_x2(unsigned* r, unsigned addr) {
    asm volatile("ldmatrix.sync.aligned.m8n8.x2.shared.b16 {%0,%1}, [%2];\n"
                 : "=r"(r[0]), "=r"(r[1]) : "r"(addr));
}
__device__ __forceinline__ void cp_async16(unsigned smem_addr, const void* gptr) {
    asm volatile("cp.async.cg.shared.global [%0], [%1], 16;\n" :: "r"(smem_addr), "l"(gptr));
}

// ---------------------------------------------------------------------------
__global__ void split4_kernel(__nv_bfloat16* __restrict__ dhi, __nv_bfloat16* __restrict__ dlo,
                              const float* __restrict__ p0, const float* __restrict__ p1,
                              const float* __restrict__ p2, const float* __restrict__ p3) {
    size_t i = (size_t)blockIdx.x * blockDim.x + threadIdx.x;
    if (i >= (size_t)G4 * HH) return;
    int g = (int)(i >> 20);
    size_t r = i & ((1u << 20) - 1);
    const float* p = (g == 0) ? p0 : (g == 1) ? p1 : (g == 2) ? p2 : p3;
    __nv_bfloat16 hi, lo;
    bsplit(p[r], hi, lo);
    dhi[i] = hi;
    dlo[i] = lo;
}

__global__ void bias_init_kernel(const float* __restrict__ bii, const float* __restrict__ bif,
                                 const float* __restrict__ big, const float* __restrict__ bio,
                                 const float* __restrict__ bhi, const float* __restrict__ bhf,
                                 const float* __restrict__ bhg, const float* __restrict__ bho) {
    int i = blockIdx.x * blockDim.x + threadIdx.x;
    if (i >= G4) return;
    int g = i >> 10, j = i & 1023;
    const float* bi = (g == 0) ? bii : (g == 1) ? bif : (g == 2) ? big : bio;
    const float* bh = (g == 0) ? bhi : (g == 1) ? bhf : (g == 2) ? bhg : bho;
    g_bias[i] = bi[j] + bh[j];
}

__global__ void init_state_kernel(const float* __restrict__ h0, const float* __restrict__ c0) {
    int i = blockIdx.x * blockDim.x + threadIdx.x;
    if (i >= BB * HH) return;
    __nv_bfloat16 hi, lo;
    bsplit(h0[i], hi, lo);
    g_hhi[0][i] = hi;
    g_hlo[0][i] = lo;
    g_c[i] = c0[i];
    if (i == 0) { g_arrive = 0; g_epoch = 0; }
}

// ---------------------------------------------------------------------------
// GEMM1 (tensor): xproj[m*4096 + n] = sum_k X[b][s][k]*Wi[n][k] + bias[n], m=(s*64+b)
#define PADK 40
__global__ void gemm1_kernel(const float* __restrict__ X) {
    __shared__ __nv_bfloat16 Ahi[128][PADK], Alo[128][PADK];
    __shared__ __nv_bfloat16 Bhi[128][PADK], Blo[128][PADK];

    const int tid = threadIdx.x;
    const int wid = tid >> 5, lane = tid & 31;
    const int grp = lane >> 2, tig = lane & 3;
    const int warpm = (wid & 3) * 32;
    const int warpn = (wid >> 2) * 64;
    const int m0 = blockIdx.y * 128;
    const int n0 = blockIdx.x * 128;

    float acc[2][8][4];
#pragma unroll
    for (int mt = 0; mt < 2; mt++)
#pragma unroll
        for (int nt = 0; nt < 8; nt++)
#pragma unroll
            for (int q = 0; q < 4; q++) acc[mt][nt][q] = 0.f;

    const int lr = tid >> 1;
    const int lkq = (tid & 1) * 16;

    for (int k0 = 0; k0 < HH; k0 += 32) {
        {
            int m = m0 + lr;
            int b = m & 63, s = m >> 6;
            const float* src = &X[(size_t)(b * SS + s) * HH + k0 + lkq];
#pragma unroll
            for (int u = 0; u < 4; u++) {
                float4 v = *reinterpret_cast<const float4*>(src + 4 * u);
                __nv_bfloat16 h0x, l0x, h1x, l1x, h2x, l2x, h3x, l3x;
                bsplit(v.x, h0x, l0x); bsplit(v.y, h1x, l1x);
                bsplit(v.z, h2x, l2x); bsplit(v.w, h3x, l3x);
                int c = lkq + 4 * u;
                Ahi[lr][c + 0] = h0x; Ahi[lr][c + 1] = h1x; Ahi[lr][c + 2] = h2x; Ahi[lr][c + 3] = h3x;
                Alo[lr][c + 0] = l0x; Alo[lr][c + 1] = l1x; Alo[lr][c + 2] = l2x; Alo[lr][c + 3] = l3x;
            }
        }
        {
            int n = n0 + lr;
            const __nv_bfloat16* shi = &g_wihi[(size_t)n * HH + k0 + lkq];
            const __nv_bfloat16* slo = &g_wilo[(size_t)n * HH + k0 + lkq];
#pragma unroll
            for (int u = 0; u < 2; u++) {
                uint4 vh = *reinterpret_cast<const uint4*>(shi + 8 * u);
                uint4 vl = *reinterpret_cast<const uint4*>(slo + 8 * u);
                *reinterpret_cast<uint4*>(&Bhi[lr][lkq + 8 * u]) = vh;
                *reinterpret_cast<uint4*>(&Blo[lr][lkq + 8 * u]) = vl;
            }
        }
        __syncthreads();

#pragma unroll
        for (int k16 = 0; k16 < 32; k16 += 16) {
            unsigned ahi[2][4], alo[2][4];
#pragma unroll
            for (int mt = 0; mt < 2; mt++) {
                int rb = warpm + mt * 16;
                ahi[mt][0] = *reinterpret_cast<const unsigned*>(&Ahi[rb + grp][k16 + 2 * tig]);
                ahi[mt][1] = *reinterpret_cast<const unsigned*>(&Ahi[rb + grp + 8][k16 + 2 * tig]);
                ahi[mt][2] = *reinterpret_cast<const unsigned*>(&Ahi[rb + grp][k16 + 2 * tig + 8]);
                ahi[mt][3] = *reinterpret_cast<const unsigned*>(&Ahi[rb + grp + 8][k16 + 2 * tig + 8]);
                alo[mt][0] = *reinterpret_cast<const unsigned*>(&Alo[rb + grp][k16 + 2 * tig]);
                alo[mt][1] = *reinterpret_cast<const unsigned*>(&Alo[rb + grp + 8][k16 + 2 * tig]);
                alo[mt][2] = *reinterpret_cast<const unsigned*>(&Alo[rb + grp][k16 + 2 * tig + 8]);
                alo[mt][3] = *reinterpret_cast<const unsigned*>(&Alo[rb + grp + 8][k16 + 2 * tig + 8]);
            }
#pragma unroll
            for (int nt = 0; nt < 8; nt++) {
                int nr = warpn + nt * 8 + grp;
                unsigned bhi[2], blo[2];
                bhi[0] = *reinterpret_cast<const unsigned*>(&Bhi[nr][k16 + 2 * tig]);
                bhi[1] = *reinterpret_cast<const unsigned*>(&Bhi[nr][k16 + 2 * tig + 8]);
                blo[0] = *reinterpret_cast<const unsigned*>(&Blo[nr][k16 + 2 * tig]);
                blo[1] = *reinterpret_cast<const unsigned*>(&Blo[nr][k16 + 2 * tig + 8]);
                mma16816(acc[0][nt], ahi[0], bhi);
                mma16816(acc[1][nt], ahi[1], bhi);
                mma16816(acc[0][nt], alo[0], bhi);
                mma16816(acc[1][nt], alo[1], bhi);
                mma16816(acc[0][nt], ahi[0], blo);
                mma16816(acc[1][nt], ahi[1], blo);
            }
        }
        __syncthreads();
    }

#pragma unroll
    for (int mt = 0; mt < 2; mt++) {
#pragma unroll
        for (int nt = 0; nt < 8; nt++) {
            int n = n0 + warpn + nt * 8 + 2 * tig;
            float bia0 = g_bias[n], bia1 = g_bias[n + 1];
            int mA = m0 + warpm + mt * 16 + grp;
            int mB = mA + 8;
            size_t rA = (size_t)mA * G4;
            size_t rB = (size_t)mB * G4;
            g_xproj[rA + n] = acc[mt][nt][0] + bia0;
            g_xproj[rA + n + 1] = acc[mt][nt][1] + bia1;
            g_xproj[rB + n] = acc[mt][nt][2] + bia0;
            g_xproj[rB + n + 1] = acc[mt][nt][3] + bia1;
        }
    }
}

// ---------------------------------------------------------------------------
// Persistent recurrence kernel with cp.async double-buffered h staging.
#define RS_BHI 0
#define RS_BLO 66048
#define RS_AHI0 132096
#define RS_ALO0 141312
#define RS_AHI1 150528
#define RS_ALO1 159744
#define RS_GSM 168960
#define RS_TOTAL 177152
#define ABUF_STRIDE 18432   // RS_AHI1 - RS_AHI0

__global__ void __launch_bounds__(256, 1) recur_kernel(float* __restrict__ out) {
    extern __shared__ unsigned char sm[];
    __nv_bfloat16(*Bhi)[1032] = reinterpret_cast<__nv_bfloat16(*)[1032]>(sm + RS_BHI);
    __nv_bfloat16(*Blo)[1032] = reinterpret_cast<__nv_bfloat16(*)[1032]>(sm + RS_BLO);
    float(*gsm)[32] = reinterpret_cast<float(*)[32]>(sm + RS_GSM);

    const int tid = threadIdx.x;
    const int wid = tid >> 5, lane = tid & 31;
    const int grp = lane >> 2, tig = lane & 3;
    const int warpm = (wid & 1) * 32;   // 0,32
    const int warpn = (wid >> 1) * 8;   // 0,8,16,24
    const int j0 = blockIdx.x * 8;
    const unsigned smbase = smem_u32(sm);

    // ---- load resident Wh slice (hi+lo), once ----
#pragma unroll
    for (int i = 0; i < 16; i++) {
        int idx = tid + i * 256;
        int row = idx >> 7;
        int c8 = (idx & 127) * 8;
        int bn = (row >> 3) * 1024 + j0 + (row & 7);
        *reinterpret_cast<uint4*>(&Bhi[row][c8]) =
            *reinterpret_cast<const uint4*>(&g_whhi[(size_t)bn * HH + c8]);
        *reinterpret_cast<uint4*>(&Blo[row][c8]) =
            *reinterpret_cast<const uint4*>(&g_whlo[(size_t)bn * HH + c8]);
    }
    __syncthreads();

    // ldmatrix lane addressing (A row stride 144 B, B row stride 2064 B)
    const int arow = (lane & 7) + ((lane >> 3) & 1) * 8;
    const int acol8 = (lane >> 4) * 8;
    const int brow = warpn + (lane & 7);
    const int bcol8 = ((lane >> 3) & 1) * 8;

    const unsigned aHiB0 = smbase + RS_AHI0 + (unsigned)(warpm + arow) * 144 + acol8 * 2;
    const unsigned aHiB1 = smbase + RS_AHI0 + (unsigned)(warpm + 16 + arow) * 144 + acol8 * 2;
    const unsigned aLoB0 = smbase + RS_ALO0 + (unsigned)(warpm + arow) * 144 + acol8 * 2;
    const unsigned aLoB1 = smbase + RS_ALO0 + (unsigned)(warpm + 16 + arow) * 144 + acol8 * 2;
    const unsigned bHiB = smbase + RS_BHI + (unsigned)brow * 2064 + bcol8 * 2;
    const unsigned bLoB = smbase + RS_BLO + (unsigned)brow * 2064 + bcol8 * 2;

    // staging addressing: thread covers rows r0 and r0+32, 16B each
    const int r0 = tid >> 3;
    const int sc8 = (tid & 7) * 8;
    const unsigned stHi0 = smbase + RS_AHI0 + (unsigned)r0 * 144 + sc8 * 2;
    const unsigned stHi1 = stHi0 + 32 * 144;
    const unsigned stLo0 = smbase + RS_ALO0 + (unsigned)r0 * 144 + sc8 * 2;
    const unsigned stLo1 = stLo0 + 32 * 144;

    for (int t = 0; t < SS; t++) {
        const int buf = t & 1;
        const __nv_bfloat16* __restrict__ hhi = g_hhi[buf];
        const __nv_bfloat16* __restrict__ hlo = g_hlo[buf];

        // early xproj prefetch (consumed at pointwise, ~whole step later)
        float xp[2][4];
#pragma unroll
        for (int uu = 0; uu < 2; uu++) {
            int u = tid + uu * 256;
            int m = u >> 3, jj = u & 7;
            const float* xb = &g_xproj[(size_t)(t * BB + m) * G4 + j0 + jj];
            xp[uu][0] = __ldcg(xb);
            xp[uu][1] = __ldcg(xb + 1024);
            xp[uu][2] = __ldcg(xb + 2048);
            xp[uu][3] = __ldcg(xb + 3072);
        }

        float acc[2][4];
#pragma unroll
        for (int mt = 0; mt < 2; mt++)
#pragma unroll
            for (int q = 0; q < 4; q++) acc[mt][q] = 0.f;

        // stage chunk 0 into buffer 0
        {
            const __nv_bfloat16* sh = &hhi[r0 * HH + sc8];
            const __nv_bfloat16* sl = &hlo[r0 * HH + sc8];
            cp_async16(stHi0, sh);
            cp_async16(stHi1, sh + 32 * HH);
            cp_async16(stLo0, sl);
            cp_async16(stLo1, sl + 32 * HH);
            asm volatile("cp.async.commit_group;\n");
        }

        for (int kc = 0; kc < 16; kc++) {
            const unsigned db = (unsigned)(kc & 1) * ABUF_STRIDE;
            if (kc < 15) {
                const int k1 = (kc + 1) * 64;
                const unsigned nb2 = (unsigned)((kc + 1) & 1) * ABUF_STRIDE;
                const __nv_bfloat16* sh = &hhi[r0 * HH + k1 + sc8];
                const __nv_bfloat16* sl = &hlo[r0 * HH + k1 + sc8];
                cp_async16(stHi0 + nb2, sh);
                cp_async16(stHi1 + nb2, sh + 32 * HH);
                cp_async16(stLo0 + nb2, sl);
                cp_async16(stLo1 + nb2, sl + 32 * HH);
                asm volatile("cp.async.commit_group;\n");
                asm volatile("cp.async.wait_group 1;\n");
            } else {
                asm volatile("cp.async.wait_group 0;\n");
            }
            __syncthreads();

#pragma unroll
            for (int k16 = 0; k16 < 4; k16++) {
                const unsigned aoff = db + k16 * 32;             // within staged chunk
                const unsigned boff = (kc * 64 + k16 * 16) * 2;  // global k byte offset
                unsigned ah0[4], ah1[4], al0[4], al1[4], bh[2], bl[2];
                ldsm_x4(ah0, aHiB0 + aoff);
                ldsm_x4(ah1, aHiB1 + aoff);
                ldsm_x4(al0, aLoB0 + aoff);
                ldsm_x4(al1, aLoB1 + aoff);
                ldsm_x2(bh, bHiB + boff);
                ldsm_x2(bl, bLoB + boff);
                mma16816(acc[0], ah0, bh);
                mma16816(acc[1], ah1, bh);
                mma16816(acc[0], al0, bh);
                mma16816(acc[1], al1, bh);
                mma16816(acc[0], ah0, bl);
                mma16816(acc[1], ah1, bl);
            }
            __syncthreads();
        }

        // stage gate results
#pragma unroll
        for (int mt = 0; mt < 2; mt++) {
            int rb = warpm + mt * 16;
            gsm[rb + grp][warpn + 2 * tig] = acc[mt][0];
            gsm[rb + grp][warpn + 2 * tig + 1] = acc[mt][1];
            gsm[rb + grp + 8][warpn + 2 * tig] = acc[mt][2];
            gsm[rb + grp + 8][warpn + 2 * tig + 1] = acc[mt][3];
        }
        __syncthreads();

        // pointwise LSTM update: 512 units, 2 per thread
        const int nb = (t + 1) & 1;
#pragma unroll
        for (int uu = 0; uu < 2; uu++) {
            int u = tid + uu * 256;
            int m = u >> 3;
            int jj = u & 7;
            float gi = gsm[m][jj] + xp[uu][0];
            float gf = gsm[m][8 + jj] + xp[uu][1];
            float gg = gsm[m][16 + jj] + xp[uu][2];
            float go = gsm[m][24 + jj] + xp[uu][3];
            float si = 1.f / (1.f + __expf(-gi));
            float sf = 1.f / (1.f + __expf(-gf));
            float tg = tanhf(gg);
            float so = 1.f / (1.f + __expf(-go));
            int idx = m * HH + j0 + jj;
            float cn = sf * g_c[idx] + si * tg;
            g_c[idx] = cn;
            float hn = so * tanhf(cn);
            out[((size_t)m * SS + t) * HH + j0 + jj] = hn;
            __nv_bfloat16 hi, lo;
            bsplit(hn, hi, lo);
            g_hhi[nb][idx] = hi;
            g_hlo[nb][idx] = lo;
            if (t == SS - 1) g_hf32[idx] = hn;
        }

        if (t == SS - 1) break;

        // ---- grid barrier: release h writes, wait for all blocks ----
        __threadfence();
        __syncthreads();
        if (tid == 0) {
            unsigned v = atomicAdd(&g_arrive, 1u) + 1u;
            if (v == (unsigned)(t + 1) * NBLK) {
                __threadfence();
                g_epoch = (unsigned)(t + 1);
            } else {
                while (g_epoch <= (unsigned)t) __nanosleep(64);
            }
            __threadfence();
        }
        __syncthreads();
    }
}

// final h/c copy into the output tail
__global__ void finalize_kernel(float* __restrict__ out) {
    int i = blockIdx.x * blockDim.x + threadIdx.x;
    if (i >= BB * HH) return;
    size_t base = (size_t)BB * SS * HH;
    out[base + i] = g_hf32[i];
    out[base + BB * HH + i] = g_c[i];
}

// ---------------------------------------------------------------------------
extern "C" void kernel_launch(void* const* d_in, const int* in_sizes, int n_in,
                              void* d_out, int out_size) {
    const float* inputs = (const float*)d_in[0];
    const float* h0 = (const float*)d_in[1];
    const float* c0 = (const float*)d_in[2];
    const float* w_ii = (const float*)d_in[3];
    const float* w_if = (const float*)d_in[4];
    const float* w_ig = (const float*)d_in[5];
    const float* w_io = (const float*)d_in[6];
    const float* b_ii = (const float*)d_in[7];
    const float* b_if = (const float*)d_in[8];
    const float* b_ig = (const float*)d_in[9];
    const float* b_io = (const float*)d_in[10];
    const float* w_hi = (const float*)d_in[11];
    const float* w_hf = (const float*)d_in[12];
    const float* w_hg = (const float*)d_in[13];
    const float* w_ho = (const float*)d_in[14];
    const float* b_hi = (const float*)d_in[15];
    const float* b_hf = (const float*)d_in[16];
    const float* b_hg = (const float*)d_in[17];
    const float* b_ho = (const float*)d_in[18];
    float* out = (float*)d_out;

    __nv_bfloat16 *wihi, *wilo, *whhi, *whlo;
    cudaGetSymbolAddress((void**)&wihi, g_wihi);
    cudaGetSymbolAddress((void**)&wilo, g_wilo);
    cudaGetSymbolAddress((void**)&whhi, g_whhi);
    cudaGetSymbolAddress((void**)&whlo, g_whlo);

    // not stream-ordered; idempotent and deterministic on every call
    cudaFuncSetAttribute(recur_kernel, cudaFuncAttributeMaxDynamicSharedMemorySize, RS_TOTAL);

    int nW = G4 * HH;
    split4_kernel<<<(nW + 255) / 256, 256>>>(wihi, wilo, w_ii, w_if, w_ig, w_io);
    split4_kernel<<<(nW + 255) / 256, 256>>>(whhi, whlo, w_hi, w_hf, w_hg, w_ho);
    bias_init_kernel<<<16, 256>>>(b_ii, b_if, b_ig, b_io, b_hi, b_hf, b_hg, b_ho);
    init_state_kernel<<<256, 256>>>(h0, c0);

    // x projection for the whole sequence (tensor cores)
    dim3 g1grid(32, 256);
    gemm1_kernel<<<g1grid, 256>>>(inputs);

    // persistent recurrence (all 512 steps)
    recur_kernel<<<NBLK, 256, RS_TOTAL>>>(out);

    if (out_size >= BB * SS * HH + 2 * BB * HH) {
        finalize_kernel<<<256, 256>>>(out);
    }
}